// round 2
// baseline (speedup 1.0000x reference)
#include <cuda_runtime.h>
#include <cstdint>
#include <cstddef>

#define DIMC 2048
#define HIDC 2730
#define HIDP 2752           // HID padded to multiple of 32 (and 16B rows)
#define NEXP 8
#define NTOK 8192
#define MAXROWS 17408       // 2*NTOK + NEXP*127 padding, rounded up

// ---------------- scratch (static __device__, no allocs) ----------------
__device__ float g_xr[(size_t)NTOK * DIMC];
__device__ float g_sw1r[(size_t)DIMC * HIDP];          // padded cols
__device__ float g_sw2r[(size_t)HIDC * DIMC];
__device__ float g_sw3r[(size_t)DIMC * HIDP];          // padded cols
__device__ float g_ew1r[(size_t)NEXP * DIMC * HIDP];   // padded cols
__device__ float g_ew2r[(size_t)NEXP * HIDC * DIMC];
__device__ float g_ew3r[(size_t)NEXP * DIMC * HIDP];   // padded cols
__device__ float g_bufA[(size_t)MAXROWS * HIDP];
__device__ float g_bufB[(size_t)MAXROWS * HIDP];
__device__ float g_y[(size_t)MAXROWS * DIMC];
__device__ int   g_counts[NEXP];
__device__ int   g_off[NEXP + 1];
__device__ int   g_cursor[NEXP];
__device__ int   g_rows[MAXROWS];
__device__ int   g_te[NTOK * 2];
__device__ int   g_slots[NTOK * 2];
__device__ float g_wts[NTOK * 2];

// ---------------- helpers ----------------
__device__ __forceinline__ float tf32r(float x) {
    float y;
    asm("cvt.rna.tf32.f32 %0, %1;" : "=f"(y) : "f"(x));
    return y;
}

__device__ __forceinline__ void cpasync16(float* dst, const float* src) {
    uint32_t d = (uint32_t)__cvta_generic_to_shared(dst);
    asm volatile("cp.async.cg.shared.global [%0], [%1], 16;\n" :: "r"(d), "l"(src));
}

__device__ __forceinline__ void mma_tf32(float c[4], const float a[4], const float b[2]) {
    asm volatile(
        "mma.sync.aligned.m16n8k8.row.col.f32.tf32.tf32.f32 "
        "{%0,%1,%2,%3}, {%4,%5,%6,%7}, {%8,%9}, {%0,%1,%2,%3};\n"
        : "+f"(c[0]), "+f"(c[1]), "+f"(c[2]), "+f"(c[3])
        : "r"(__float_as_uint(a[0])), "r"(__float_as_uint(a[1])),
          "r"(__float_as_uint(a[2])), "r"(__float_as_uint(a[3])),
          "r"(__float_as_uint(b[0])), "r"(__float_as_uint(b[1])));
}

// ---------------- small kernels ----------------
// tf32-round, same layout (for 16B-aligned-stride tensors)
__global__ void k_round(const float* __restrict__ in, float* __restrict__ out, int n4) {
    int i = blockIdx.x * blockDim.x + threadIdx.x;
    if (i >= n4) return;
    float4 v = reinterpret_cast<const float4*>(in)[i];
    v.x = tf32r(v.x); v.y = tf32r(v.y); v.z = tf32r(v.z); v.w = tf32r(v.w);
    reinterpret_cast<float4*>(out)[i] = v;
}

// tf32-round + repad rows from HIDC stride to HIDP stride (zero pad cols)
__global__ void k_round_pad(const float* __restrict__ in, float* __restrict__ out, long nrows) {
    long i = (long)blockIdx.x * blockDim.x + threadIdx.x;   // float2 index in output
    long tot = nrows * (HIDP / 2);
    if (i >= tot) return;
    long row = i / (HIDP / 2);
    int  col = (int)(i % (HIDP / 2)) * 2;
    float2 o = make_float2(0.f, 0.f);
    if (col < HIDC) {   // HIDC even -> col, col+1 both in-range together
        float2 v = *reinterpret_cast<const float2*>(in + row * HIDC + col);
        o.x = tf32r(v.x); o.y = tf32r(v.y);
    }
    *reinterpret_cast<float2*>(out + row * HIDP + col) = o;
}

__global__ void k_init() {
    int i = blockIdx.x * blockDim.x + threadIdx.x;
    if (i < NEXP) g_counts[i] = 0;
    if (i < MAXROWS) g_rows[i] = 0;
}

// one warp per token: logits = x . router_w, top-2, renormalized weights
__global__ void k_router(const float* __restrict__ x, const float* __restrict__ rw) {
    int gt = blockIdx.x * blockDim.x + threadIdx.x;
    int warp = gt >> 5;
    int lane = gt & 31;
    if (warp >= NTOK) return;
    const float* xr = x + (size_t)warp * DIMC;
    float acc[8] = {0.f,0.f,0.f,0.f,0.f,0.f,0.f,0.f};
    for (int i = 0; i < DIMC / 32; i++) {
        int d = i * 32 + lane;
        float xv = xr[d];
        const float4* p = reinterpret_cast<const float4*>(rw + (size_t)d * NEXP);
        float4 r0 = p[0], r1 = p[1];
        acc[0] += xv * r0.x; acc[1] += xv * r0.y; acc[2] += xv * r0.z; acc[3] += xv * r0.w;
        acc[4] += xv * r1.x; acc[5] += xv * r1.y; acc[6] += xv * r1.z; acc[7] += xv * r1.w;
    }
    #pragma unroll
    for (int e = 0; e < 8; e++) {
        #pragma unroll
        for (int o = 16; o > 0; o >>= 1) acc[e] += __shfl_xor_sync(0xffffffffu, acc[e], o);
    }
    if (lane == 0) {
        int e0 = 0; float l0 = acc[0];
        #pragma unroll
        for (int e = 1; e < 8; e++) if (acc[e] > l0) { l0 = acc[e]; e0 = e; }
        int e1 = 0; float l1 = -3.4e38f;
        #pragma unroll
        for (int e = 0; e < 8; e++) if (e != e0 && acc[e] > l1) { l1 = acc[e]; e1 = e; }
        // renormalized top-2 softmax weights: w0 = 1/(1+exp(l1-l0))
        float w0 = 1.f / (1.f + __expf(l1 - l0));
        g_te[2 * warp] = e0; g_te[2 * warp + 1] = e1;
        g_wts[2 * warp] = w0; g_wts[2 * warp + 1] = 1.f - w0;
        atomicAdd(&g_counts[e0], 1);
        atomicAdd(&g_counts[e1], 1);
    }
}

// 128-aligned exclusive scan of expert counts (single thread; 8 entries)
__global__ void k_scan() {
    if (threadIdx.x == 0 && blockIdx.x == 0) {
        int o = 0;
        for (int e = 0; e < NEXP; e++) {
            g_off[e] = o;
            g_cursor[e] = o;
            o += (g_counts[e] + 127) & ~127;
        }
        g_off[NEXP] = o;
    }
}

__global__ void k_assign() {
    int t = blockIdx.x * blockDim.x + threadIdx.x;
    if (t >= NTOK) return;
    #pragma unroll
    for (int k = 0; k < 2; k++) {
        int e = g_te[2 * t + k];
        int p = atomicAdd(&g_cursor[e], 1);
        g_rows[p] = t;
        g_slots[2 * t + k] = p;
    }
}

// h = tf32round(silu(a) * b); zero the pad columns [HIDC, HIDP)
__global__ void k_silumul(const float* __restrict__ a, const float* __restrict__ b,
                          float* __restrict__ h, int nrows) {
    size_t i = (size_t)blockIdx.x * blockDim.x + threadIdx.x;
    size_t tot = (size_t)nrows * (HIDP / 4);
    if (i >= tot) return;
    int c4 = (int)(i % (HIDP / 4)) * 4;
    float4 av = reinterpret_cast<const float4*>(a)[i];
    float4 bv = reinterpret_cast<const float4*>(b)[i];
    float4 o;
    o.x = (c4 + 0 < HIDC) ? tf32r(av.x / (1.f + __expf(-av.x)) * bv.x) : 0.f;
    o.y = (c4 + 1 < HIDC) ? tf32r(av.y / (1.f + __expf(-av.y)) * bv.y) : 0.f;
    o.z = (c4 + 2 < HIDC) ? tf32r(av.z / (1.f + __expf(-av.z)) * bv.z) : 0.f;
    o.w = (c4 + 3 < HIDC) ? tf32r(av.w / (1.f + __expf(-av.w)) * bv.w) : 0.f;
    reinterpret_cast<float4*>(h)[i] = o;
}

// out[t] += w0*Y[slot0] + w1*Y[slot1]
__global__ void k_combine(float* __restrict__ out) {
    int i = blockIdx.x * blockDim.x + threadIdx.x;
    if (i >= NTOK * (DIMC / 4)) return;
    int t = i / (DIMC / 4);
    int c4 = i % (DIMC / 4);
    int s0 = g_slots[2 * t], s1 = g_slots[2 * t + 1];
    float w0 = g_wts[2 * t], w1 = g_wts[2 * t + 1];
    float4 y0 = reinterpret_cast<const float4*>(g_y + (size_t)s0 * DIMC)[c4];
    float4 y1 = reinterpret_cast<const float4*>(g_y + (size_t)s1 * DIMC)[c4];
    float4 o = reinterpret_cast<float4*>(out)[i];
    o.x += w0 * y0.x + w1 * y1.x;
    o.y += w0 * y0.y + w1 * y1.y;
    o.z += w0 * y0.z + w1 * y1.z;
    o.w += w0 * y0.w + w1 * y1.w;
    reinterpret_cast<float4*>(out)[i] = o;
}

// ---------------- TF32 GEMM: C = A @ B, 128x128x32 tiles, cp.async 2-stage ----
// GATHER: A rows indirected through g_rows. EXPERT: blockIdx.z selects expert,
// m-range from g_off (128-aligned), B offset by bStride.
// NOTE: ldb MUST give 16B-aligned row starts (ldb % 4 == 0).
template <bool GATHER, bool EXPERT>
__global__ void __launch_bounds__(256)
k_gemm(const float* __restrict__ A, const float* __restrict__ B,
       float* __restrict__ C, int N, int K, int Kb,
       int lda, int ldb, int ldc, long bStride) {
    extern __shared__ float sm[];
    float* As = sm;                    // 2 stages * 128 * 36
    float* Bs = sm + 2 * 128 * 36;     // 2 stages * 32 * 132
    __shared__ int rIdx[128];

    int e = blockIdx.z;
    int off = 0;
    if (EXPERT) {
        off = g_off[e];
        int mcount = g_off[e + 1] - off;
        if ((int)blockIdx.y * 128 >= mcount) return;
    }
    int bm = blockIdx.y, bn = blockIdx.x;
    int tid = threadIdx.x;
    const float* Bt = B + (size_t)e * bStride;

    if (tid < 128) {
        int r = off + bm * 128 + tid;
        rIdx[tid] = GATHER ? g_rows[r] : r;
    }
    __syncthreads();

    int arow = tid >> 3;            // 0..31
    int acol = (tid & 7) * 4;       // 0..28
    const float* aptr[4];
    #pragma unroll
    for (int i = 0; i < 4; i++)
        aptr[i] = A + (size_t)rIdx[arow + i * 32] * lda + acol;

    int brow = tid >> 5;            // 0..7
    int bcol = (tid & 31) * 4;      // 0..124
    int ncol = bn * 128 + bcol;

    auto loadStage = [&](int kt, int s) {
        int k0 = kt * 32;
        float* Ad = As + s * (128 * 36);
        #pragma unroll
        for (int i = 0; i < 4; i++)
            cpasync16(Ad + (arow + i * 32) * 36 + acol, aptr[i] + k0);
        float* Bd = Bs + s * (32 * 132);
        #pragma unroll
        for (int i = 0; i < 4; i++) {
            int kr = brow + i * 8;
            float* d = Bd + kr * 132 + bcol;
            int kg = k0 + kr;
            if (kg < Kb && ncol + 3 < N) {
                cpasync16(d, Bt + (size_t)kg * ldb + ncol);
            } else if (kg < Kb && ncol < N) {
                #pragma unroll
                for (int j = 0; j < 4; j++)
                    d[j] = (ncol + j < N) ? Bt[(size_t)kg * ldb + ncol + j] : 0.f;
            } else {
                d[0] = 0.f; d[1] = 0.f; d[2] = 0.f; d[3] = 0.f;
            }
        }
        asm volatile("cp.async.commit_group;\n");
    };

    float c[4][4][4] = {};
    int lane = tid & 31, g = lane >> 2, t4 = lane & 3;
    int warp = tid >> 5, wm = warp >> 2, wn = warp & 3;

    int KT = K / 32;
    loadStage(0, 0);
    for (int kt = 0; kt < KT; kt++) {
        asm volatile("cp.async.wait_group 0;\n");
        __syncthreads();
        int s = kt & 1;
        if (kt + 1 < KT) loadStage(kt + 1, s ^ 1);
        const float* Ab = As + s * (128 * 36);
        const float* Bb = Bs + s * (32 * 132);
        #pragma unroll
        for (int kk = 0; kk < 32; kk += 8) {
            float a[4][4], b[4][2];
            #pragma unroll
            for (int mt = 0; mt < 4; mt++) {
                int mr = wm * 64 + mt * 16;
                a[mt][0] = Ab[(mr + g) * 36 + kk + t4];
                a[mt][1] = Ab[(mr + g + 8) * 36 + kk + t4];
                a[mt][2] = Ab[(mr + g) * 36 + kk + t4 + 4];
                a[mt][3] = Ab[(mr + g + 8) * 36 + kk + t4 + 4];
            }
            #pragma unroll
            for (int nt = 0; nt < 4; nt++) {
                int nc = wn * 32 + nt * 8;
                b[nt][0] = Bb[(kk + t4) * 132 + nc + g];
                b[nt][1] = Bb[(kk + t4 + 4) * 132 + nc + g];
            }
            #pragma unroll
            for (int mt = 0; mt < 4; mt++)
                #pragma unroll
                for (int nt = 0; nt < 4; nt++)
                    mma_tf32(c[mt][nt], a[mt], b[nt]);
        }
        __syncthreads();
    }

    #pragma unroll
    for (int mt = 0; mt < 4; mt++) {
        int rr = off + bm * 128 + wm * 64 + mt * 16 + g;
        #pragma unroll
        for (int nt = 0; nt < 4; nt++) {
            int cc = bn * 128 + wn * 32 + nt * 8 + 2 * t4;
            if (cc < N) {
                *reinterpret_cast<float2*>(C + (size_t)rr * ldc + cc) =
                    make_float2(c[mt][nt][0], c[mt][nt][1]);
                *reinterpret_cast<float2*>(C + (size_t)(rr + 8) * ldc + cc) =
                    make_float2(c[mt][nt][2], c[mt][nt][3]);
            }
        }
    }
}

// ---------------- host ----------------
extern "C" void kernel_launch(void* const* d_in, const int* in_sizes, int n_in,
                              void* d_out, int out_size) {
    const float* x   = (const float*)d_in[0];
    const float* rw  = (const float*)d_in[1];
    const float* sw1 = (const float*)d_in[2];
    const float* sw2 = (const float*)d_in[3];
    const float* sw3 = (const float*)d_in[4];
    const float* ew1 = (const float*)d_in[5];
    const float* ew2 = (const float*)d_in[6];
    const float* ew3 = (const float*)d_in[7];
    float* out = (float*)d_out;

    float *xr, *s1, *s2, *s3, *e1p, *e2p, *e3p, *bA, *bB, *yb;
    cudaGetSymbolAddress((void**)&xr,  g_xr);
    cudaGetSymbolAddress((void**)&s1,  g_sw1r);
    cudaGetSymbolAddress((void**)&s2,  g_sw2r);
    cudaGetSymbolAddress((void**)&s3,  g_sw3r);
    cudaGetSymbolAddress((void**)&e1p, g_ew1r);
    cudaGetSymbolAddress((void**)&e2p, g_ew2r);
    cudaGetSymbolAddress((void**)&e3p, g_ew3r);
    cudaGetSymbolAddress((void**)&bA,  g_bufA);
    cudaGetSymbolAddress((void**)&bB,  g_bufB);
    cudaGetSymbolAddress((void**)&yb,  g_y);

    const size_t smemSz = (2 * 128 * 36 + 2 * 32 * 132) * sizeof(float); // 70656B
    cudaFuncSetAttribute(k_gemm<false, false>, cudaFuncAttributeMaxDynamicSharedMemorySize, (int)smemSz);
    cudaFuncSetAttribute(k_gemm<true,  true >, cudaFuncAttributeMaxDynamicSharedMemorySize, (int)smemSz);
    cudaFuncSetAttribute(k_gemm<false, true >, cudaFuncAttributeMaxDynamicSharedMemorySize, (int)smemSz);

    k_init<<<(MAXROWS + 255) / 256, 256>>>();

    auto rnd = [](const float* i, float* o, size_t n) {
        int n4 = (int)(n / 4);
        k_round<<<(n4 + 255) / 256, 256>>>(i, o, n4);
    };
    auto rndpad = [](const float* i, float* o, long nrows) {
        long tot = nrows * (HIDP / 2);
        k_round_pad<<<(unsigned)((tot + 255) / 256), 256>>>(i, o, nrows);
    };
    rnd(x,   xr,  (size_t)NTOK * DIMC);
    rnd(sw2, s2,  (size_t)HIDC * DIMC);
    rnd(ew2, e2p, (size_t)NEXP * HIDC * DIMC);
    rndpad(sw1, s1,  DIMC);                 // [DIMC,HIDC] -> [DIMC,HIDP]
    rndpad(sw3, s3,  DIMC);
    rndpad(ew1, e1p, (long)NEXP * DIMC);    // [E*DIMC,HIDC] -> [E*DIMC,HIDP]
    rndpad(ew3, e3p, (long)NEXP * DIMC);

    k_router<<<(NTOK * 32 + 255) / 256, 256>>>(x, rw);
    k_scan<<<1, 32>>>();
    k_assign<<<(NTOK + 255) / 256, 256>>>();

    dim3 blk(256);

    // ---- shared expert ----
    {
        dim3 grid((HIDC + 127) / 128, NTOK / 128, 1);
        k_gemm<false, false><<<grid, blk, smemSz>>>(xr, s1, bA, HIDC, DIMC, DIMC, DIMC, HIDP, HIDP, 0L);
        k_gemm<false, false><<<grid, blk, smemSz>>>(xr, s3, bB, HIDC, DIMC, DIMC, DIMC, HIDP, HIDP, 0L);
    }
    {
        size_t tot = (size_t)NTOK * (HIDP / 4);
        k_silumul<<<(unsigned)((tot + 255) / 256), 256>>>(bA, bB, bA, NTOK);
    }
    {
        dim3 grid(DIMC / 128, NTOK / 128, 1);
        k_gemm<false, false><<<grid, blk, smemSz>>>(bA, s2, out, DIMC, HIDP, HIDC, HIDP, DIMC, DIMC, 0L);
    }

    // ---- routed experts (gathered token rows, device-side counts) ----
    {
        dim3 grid((HIDC + 127) / 128, NTOK / 128, NEXP);
        k_gemm<true, true><<<grid, blk, smemSz>>>(xr, e1p, bA, HIDC, DIMC, DIMC, DIMC, HIDP, HIDP, (long)DIMC * HIDP);
        k_gemm<true, true><<<grid, blk, smemSz>>>(xr, e3p, bB, HIDC, DIMC, DIMC, DIMC, HIDP, HIDP, (long)DIMC * HIDP);
    }
    {
        size_t tot = (size_t)MAXROWS * (HIDP / 4);
        k_silumul<<<(unsigned)((tot + 255) / 256), 256>>>(bA, bB, bA, MAXROWS);
    }
    {
        dim3 grid(DIMC / 128, NTOK / 128, NEXP);
        k_gemm<false, true><<<grid, blk, smemSz>>>(bA, e2p, yb, DIMC, HIDP, HIDC, HIDP, DIMC, DIMC, (long)HIDC * DIMC);
    }

    k_combine<<<(NTOK * (DIMC / 4) + 255) / 256, 256>>>(out);
}

// round 6
// speedup vs baseline: 1.3260x; 1.3260x over previous
#include <cuda_runtime.h>
#include <cuda_fp16.h>
#include <cstdint>
#include <cstddef>

#define DIMC 2048
#define HIDC 2730
#define HP   2816           // HID padded to multiple of 128 (N-tile) and 32 (K-chunk)
#define HP2  (2 * HP)       // gate+up concatenated
#define NEXP 8
#define NTOK 8192
#define MAXROWS 17408       // 2*NTOK + NEXP*127, rounded up to 128

// ---------------- scratch (static __device__, no allocs) ----------------
__device__ __half g_xh[(size_t)NTOK * DIMC];
__device__ __half g_w13T[(size_t)HP2 * DIMC];            // [N=2HP, K=DIMC] (w1 rows 0..HP-1, w3 rows HP..)
__device__ __half g_w2T[(size_t)DIMC * HP];              // [N=DIMC, K=HP] (K zero-padded)
__device__ __half g_e13T[(size_t)NEXP * HP2 * DIMC];
__device__ __half g_e2T[(size_t)NEXP * DIMC * HP];
__device__ float  g_gu[(size_t)MAXROWS * HP2];           // gate|up GEMM output (fp32)
__device__ __half g_h[(size_t)MAXROWS * HP];             // silu(gate)*up (half)
__device__ float  g_y[(size_t)MAXROWS * DIMC];
__device__ int    g_counts[NEXP];
__device__ int    g_off[NEXP + 1];
__device__ int    g_cursor[NEXP];
__device__ int    g_rows[MAXROWS];
__device__ int    g_te[NTOK * 2];
__device__ int    g_slots[NTOK * 2];
__device__ float  g_wts[NTOK * 2];

// ---------------- helpers ----------------
__device__ __forceinline__ void cpasync16(uint32_t dst, const void* src) {
    asm volatile("cp.async.cg.shared.global [%0], [%1], 16;\n" :: "r"(dst), "l"(src));
}

__device__ __forceinline__ uint32_t lds32(uint32_t a) {
    uint32_t v;
    asm volatile("ld.shared.b32 %0, [%1];" : "=r"(v) : "r"(a));
    return v;
}

// smem byte offset for (row, kp) where kp = half2 index 0..15 within a 32-half row.
// XOR swizzle on the 16B-chunk index with row bits 1-2 -> conflict-free fragment LDS.
__device__ __forceinline__ uint32_t swb(int row, int kp) {
    return (uint32_t)(row * 64 + ((kp & 3) << 2) + (((((kp >> 2)) ^ ((row >> 1) & 3)) & 3) << 4));
}
// 16B-chunk destination for cp.async: chunk index c (0..3) in row
__device__ __forceinline__ uint32_t swdst(int row, int c) {
    return (uint32_t)(row * 64 + ((c ^ ((row >> 1) & 3)) << 4));
}

__device__ __forceinline__ void mma_f16(float c[4], const uint32_t a[4], const uint32_t b[2]) {
    asm volatile(
        "mma.sync.aligned.m16n8k16.row.col.f32.f16.f16.f32 "
        "{%0,%1,%2,%3}, {%4,%5,%6,%7}, {%8,%9}, {%0,%1,%2,%3};\n"
        : "+f"(c[0]), "+f"(c[1]), "+f"(c[2]), "+f"(c[3])
        : "r"(a[0]), "r"(a[1]), "r"(a[2]), "r"(a[3]), "r"(b[0]), "r"(b[1]));
}

// ---------------- small kernels ----------------
__global__ void k_tohalf(const float* __restrict__ in, __half* __restrict__ out, long n4) {
    long i = (long)blockIdx.x * blockDim.x + threadIdx.x;
    if (i >= n4) return;
    float4 v = reinterpret_cast<const float4*>(in)[i];
    __half2 h0 = __floats2half2_rn(v.x, v.y);
    __half2 h1 = __floats2half2_rn(v.z, v.w);
    uint2 u;
    u.x = *reinterpret_cast<uint32_t*>(&h0);
    u.y = *reinterpret_cast<uint32_t*>(&h1);
    reinterpret_cast<uint2*>(out)[i] = u;
}

// out[c, r] = (c<C && r<R) ? half(in[r, c]) : 0   (out is [CP x RP] half, batched over z)
__global__ void k_trans(const float* __restrict__ in, __half* __restrict__ out,
                        int R, int C, int CP, int RP, long inStride, long outStride) {
    __shared__ float t[32][33];
    const float* ip = in + (size_t)blockIdx.z * inStride;
    __half* op = out + (size_t)blockIdx.z * outStride;
    int c0 = blockIdx.x * 32, r0 = blockIdx.y * 32;
    int tx = threadIdx.x, ty = threadIdx.y;   // 32 x 8
    #pragma unroll
    for (int i = 0; i < 32; i += 8) {
        int r = r0 + ty + i, c = c0 + tx;
        t[ty + i][tx] = (r < R && c < C) ? ip[(size_t)r * C + c] : 0.f;
    }
    __syncthreads();
    #pragma unroll
    for (int i = 0; i < 32; i += 8) {
        int oc = c0 + ty + i, orr = r0 + tx;
        if (oc < CP && orr < RP)
            op[(size_t)oc * RP + orr] = __float2half_rn(t[tx][ty + i]);
    }
}

__global__ void k_init() {
    int i = blockIdx.x * blockDim.x + threadIdx.x;
    if (i < NEXP) g_counts[i] = 0;
    if (i < MAXROWS) g_rows[i] = 0;
}

__global__ void k_router(const float* __restrict__ x, const float* __restrict__ rw) {
    int gt = blockIdx.x * blockDim.x + threadIdx.x;
    int warp = gt >> 5;
    int lane = gt & 31;
    if (warp >= NTOK) return;
    const float* xr = x + (size_t)warp * DIMC;
    float acc[8] = {0.f,0.f,0.f,0.f,0.f,0.f,0.f,0.f};
    for (int i = 0; i < DIMC / 32; i++) {
        int d = i * 32 + lane;
        float xv = xr[d];
        const float4* p = reinterpret_cast<const float4*>(rw + (size_t)d * NEXP);
        float4 r0 = p[0], r1 = p[1];
        acc[0] += xv * r0.x; acc[1] += xv * r0.y; acc[2] += xv * r0.z; acc[3] += xv * r0.w;
        acc[4] += xv * r1.x; acc[5] += xv * r1.y; acc[6] += xv * r1.z; acc[7] += xv * r1.w;
    }
    #pragma unroll
    for (int e = 0; e < 8; e++) {
        #pragma unroll
        for (int o = 16; o > 0; o >>= 1) acc[e] += __shfl_xor_sync(0xffffffffu, acc[e], o);
    }
    if (lane == 0) {
        int e0 = 0; float l0 = acc[0];
        #pragma unroll
        for (int e = 1; e < 8; e++) if (acc[e] > l0) { l0 = acc[e]; e0 = e; }
        int e1 = 0; float l1 = -3.4e38f;
        #pragma unroll
        for (int e = 0; e < 8; e++) if (e != e0 && acc[e] > l1) { l1 = acc[e]; e1 = e; }
        float w0 = 1.f / (1.f + __expf(l1 - l0));
        g_te[2 * warp] = e0; g_te[2 * warp + 1] = e1;
        g_wts[2 * warp] = w0; g_wts[2 * warp + 1] = 1.f - w0;
        atomicAdd(&g_counts[e0], 1);
        atomicAdd(&g_counts[e1], 1);
    }
}

__global__ void k_scan() {
    if (threadIdx.x == 0 && blockIdx.x == 0) {
        int o = 0;
        for (int e = 0; e < NEXP; e++) {
            g_off[e] = o;
            g_cursor[e] = o;
            o += (g_counts[e] + 127) & ~127;
        }
        g_off[NEXP] = o;
    }
}

__global__ void k_assign() {
    int t = blockIdx.x * blockDim.x + threadIdx.x;
    if (t >= NTOK) return;
    #pragma unroll
    for (int k = 0; k < 2; k++) {
        int e = g_te[2 * t + k];
        int p = atomicAdd(&g_cursor[e], 1);
        g_rows[p] = t;
        g_slots[2 * t + k] = p;
    }
}

// h[row, c] = half(silu(gu[row, c]) * gu[row, HP + c]) for 4 cols per thread
__global__ void k_silumul(const float* __restrict__ gu, __half* __restrict__ h, long n4) {
    long i = (long)blockIdx.x * blockDim.x + threadIdx.x;
    if (i >= n4) return;
    long row = i / (HP / 4);
    int c4 = (int)(i % (HP / 4)) * 4;
    const float4 gv = *reinterpret_cast<const float4*>(gu + row * HP2 + c4);
    const float4 uv = *reinterpret_cast<const float4*>(gu + row * HP2 + HP + c4);
    float ox = gv.x / (1.f + __expf(-gv.x)) * uv.x;
    float oy = gv.y / (1.f + __expf(-gv.y)) * uv.y;
    float oz = gv.z / (1.f + __expf(-gv.z)) * uv.z;
    float ow = gv.w / (1.f + __expf(-gv.w)) * uv.w;
    __half2 h0 = __floats2half2_rn(ox, oy);
    __half2 h1 = __floats2half2_rn(oz, ow);
    uint2 u;
    u.x = *reinterpret_cast<uint32_t*>(&h0);
    u.y = *reinterpret_cast<uint32_t*>(&h1);
    *reinterpret_cast<uint2*>(h + row * HP + c4) = u;
}

__global__ void k_combine(float* __restrict__ out) {
    int i = blockIdx.x * blockDim.x + threadIdx.x;
    if (i >= NTOK * (DIMC / 4)) return;
    int t = i / (DIMC / 4);
    int c4 = i % (DIMC / 4);
    int s0 = g_slots[2 * t], s1 = g_slots[2 * t + 1];
    float w0 = g_wts[2 * t], w1 = g_wts[2 * t + 1];
    float4 y0 = reinterpret_cast<const float4*>(g_y + (size_t)s0 * DIMC)[c4];
    float4 y1 = reinterpret_cast<const float4*>(g_y + (size_t)s1 * DIMC)[c4];
    float4 o = reinterpret_cast<float4*>(out)[i];
    o.x += w0 * y0.x + w1 * y1.x;
    o.y += w0 * y0.y + w1 * y1.y;
    o.z += w0 * y0.z + w1 * y1.z;
    o.w += w0 * y0.w + w1 * y1.w;
    reinterpret_cast<float4*>(out)[i] = o;
}

// ---------------- FP16 GEMM: C = A @ B^T, tiles 128x128x32, 3-stage cp.async --
// A: [rows, K] half (rows via rIdx if GATHER). B: [N, K] half (K-major).
// EXPERT: blockIdx.z selects expert; m-range from g_off (128-aligned).
#define NSTG 3
#define TILE_BYTES 8192          // 128 rows * 64B (32 halves)
#define STG_BYTES  16384         // A + B tile
#define DYN_BYTES  (NSTG * STG_BYTES)

template <bool GATHER, bool EXPERT>
__global__ void __launch_bounds__(256, 2)
k_hgemm(const __half* __restrict__ A, const __half* __restrict__ B,
        float* __restrict__ C, int K, int lda, int ldb, int ldc, long bStride) {
    extern __shared__ char smemRaw[];
    __shared__ int rIdx[128];

    int z = blockIdx.z;
    int off = 0;
    if (EXPERT) {
        off = g_off[z];
        int mcount = g_off[z + 1] - off;
        if ((int)blockIdx.y * 128 >= mcount) return;
    }
    int bm = blockIdx.y, bn = blockIdx.x;
    int tid = threadIdx.x;
    int lane = tid & 31, warp = tid >> 5;
    int g = lane >> 2, t4 = lane & 3;
    int wm = warp >> 1, wn = warp & 1;

    uint32_t base = (uint32_t)__cvta_generic_to_shared(smemRaw);

    if (tid < 128) {
        int r = off + bm * 128 + tid;
        rIdx[tid] = GATHER ? g_rows[r] : r;
    }
    __syncthreads();

    // per-thread load assignment: row = tid&127, two 16B chunks (tid>>7 selects pair)
    int lrow = tid & 127;
    int cpair = (tid >> 7) * 2;          // chunks cpair, cpair+1 (each 8 halves)
    const __half* agp = A + (size_t)rIdx[lrow] * lda + cpair * 8;
    const __half* Bt = B + (size_t)z * bStride;
    const __half* bgp = Bt + (size_t)(bn * 128 + lrow) * ldb + cpair * 8;

    auto loadStage = [&](int kt, int s) {
        int k0 = kt * 32;
        uint32_t sa = base + s * STG_BYTES;
        uint32_t sb = sa + TILE_BYTES;
        cpasync16(sa + swdst(lrow, cpair),     agp + k0);
        cpasync16(sa + swdst(lrow, cpair + 1), agp + k0 + 8);
        cpasync16(sb + swdst(lrow, cpair),     bgp + k0);
        cpasync16(sb + swdst(lrow, cpair + 1), bgp + k0 + 8);
        asm volatile("cp.async.commit_group;\n");
    };

    float c[2][8][4] = {};

    int KT = K >> 5;
    loadStage(0, 0);
    loadStage(1, 1);
    for (int kt = 0; kt < KT; kt++) {
        asm volatile("cp.async.wait_group %0;\n" :: "n"(1));
        __syncthreads();
        if (kt + 2 < KT) loadStage(kt + 2, (kt + 2) % NSTG);
        else asm volatile("cp.async.commit_group;\n");
        int s = kt % NSTG;
        uint32_t sa = base + s * STG_BYTES;
        uint32_t sb = sa + TILE_BYTES;
        #pragma unroll
        for (int kk = 0; kk < 2; kk++) {
            int kp0 = kk * 8 + t4;
            uint32_t a[2][4];
            #pragma unroll
            for (int mt = 0; mt < 2; mt++) {
                int r0 = wm * 32 + mt * 16 + g;
                a[mt][0] = lds32(sa + swb(r0,     kp0));
                a[mt][1] = lds32(sa + swb(r0 + 8, kp0));
                a[mt][2] = lds32(sa + swb(r0,     kp0 + 4));
                a[mt][3] = lds32(sa + swb(r0 + 8, kp0 + 4));
            }
            uint32_t bf[8][2];
            #pragma unroll
            for (int nt = 0; nt < 8; nt++) {
                int nr = wn * 64 + nt * 8 + g;
                bf[nt][0] = lds32(sb + swb(nr, kp0));
                bf[nt][1] = lds32(sb + swb(nr, kp0 + 4));
            }
            #pragma unroll
            for (int mt = 0; mt < 2; mt++)
                #pragma unroll
                for (int nt = 0; nt < 8; nt++)
                    mma_f16(c[mt][nt], a[mt], bf[nt]);
        }
        __syncthreads();
    }

    // epilogue: direct float2 stores
    #pragma unroll
    for (int mt = 0; mt < 2; mt++) {
        int rr = off + bm * 128 + wm * 32 + mt * 16 + g;
        #pragma unroll
        for (int nt = 0; nt < 8; nt++) {
            int cc = bn * 128 + wn * 64 + nt * 8 + 2 * t4;
            *reinterpret_cast<float2*>(C + (size_t)rr * ldc + cc) =
                make_float2(c[mt][nt][0], c[mt][nt][1]);
            *reinterpret_cast<float2*>(C + (size_t)(rr + 8) * ldc + cc) =
                make_float2(c[mt][nt][2], c[mt][nt][3]);
        }
    }
}

// ---------------- host ----------------
extern "C" void kernel_launch(void* const* d_in, const int* in_sizes, int n_in,
                              void* d_out, int out_size) {
    const float* x   = (const float*)d_in[0];
    const float* rw  = (const float*)d_in[1];
    const float* sw1 = (const float*)d_in[2];
    const float* sw2 = (const float*)d_in[3];
    const float* sw3 = (const float*)d_in[4];
    const float* ew1 = (const float*)d_in[5];
    const float* ew2 = (const float*)d_in[6];
    const float* ew3 = (const float*)d_in[7];
    float* out = (float*)d_out;

    __half *xh, *w13, *w2t, *e13, *e2t, *hbuf;
    float *gu, *yb;
    cudaGetSymbolAddress((void**)&xh,   g_xh);
    cudaGetSymbolAddress((void**)&w13,  g_w13T);
    cudaGetSymbolAddress((void**)&w2t,  g_w2T);
    cudaGetSymbolAddress((void**)&e13,  g_e13T);
    cudaGetSymbolAddress((void**)&e2t,  g_e2T);
    cudaGetSymbolAddress((void**)&hbuf, g_h);
    cudaGetSymbolAddress((void**)&gu,   g_gu);
    cudaGetSymbolAddress((void**)&yb,   g_y);

    cudaFuncSetAttribute(k_hgemm<false, false>, cudaFuncAttributeMaxDynamicSharedMemorySize, DYN_BYTES);
    cudaFuncSetAttribute(k_hgemm<true,  true >, cudaFuncAttributeMaxDynamicSharedMemorySize, DYN_BYTES);
    cudaFuncSetAttribute(k_hgemm<false, true >, cudaFuncAttributeMaxDynamicSharedMemorySize, DYN_BYTES);

    k_init<<<(MAXROWS + 255) / 256, 256>>>();

    // x -> half
    k_tohalf<<<((NTOK * DIMC / 4) + 255) / 256, 256>>>(x, xh, (long)NTOK * DIMC / 4);

    // weights -> [N, K] half, transposed + padded
    dim3 tb(32, 8);
    // w1/w3 (in [DIMC, HIDC]) -> rows [0,HP) / [HP,2HP) of w13T [2HP, DIMC]
    k_trans<<<dim3(HP / 32, DIMC / 32, 1), tb>>>(sw1, w13,            DIMC, HIDC, HP, DIMC, 0, 0);
    k_trans<<<dim3(HP / 32, DIMC / 32, 1), tb>>>(sw3, w13 + (size_t)HP * DIMC, DIMC, HIDC, HP, DIMC, 0, 0);
    k_trans<<<dim3(HP / 32, DIMC / 32, NEXP), tb>>>(ew1, e13, DIMC, HIDC, HP, DIMC,
                                                    (long)DIMC * HIDC, (long)HP2 * DIMC);
    k_trans<<<dim3(HP / 32, DIMC / 32, NEXP), tb>>>(ew3, e13 + (size_t)HP * DIMC, DIMC, HIDC, HP, DIMC,
                                                    (long)DIMC * HIDC, (long)HP2 * DIMC);
    // w2 (in [HIDC, DIMC]) -> w2T [DIMC, HP] (K padded with zeros)
    k_trans<<<dim3(DIMC / 32, HP / 32, 1), tb>>>(sw2, w2t, HIDC, DIMC, DIMC, HP, 0, 0);
    k_trans<<<dim3(DIMC / 32, HP / 32, NEXP), tb>>>(ew2, e2t, HIDC, DIMC, DIMC, HP,
                                                    (long)HIDC * DIMC, (long)DIMC * HP);

    k_router<<<(NTOK * 32 + 255) / 256, 256>>>(x, rw);
    k_scan<<<1, 32>>>();
    k_assign<<<(NTOK + 255) / 256, 256>>>();

    // ---- shared expert ----
    k_hgemm<false, false><<<dim3(HP2 / 128, NTOK / 128, 1), 256, DYN_BYTES>>>(
        xh, w13, gu, DIMC, DIMC, DIMC, HP2, 0L);
    k_silumul<<<(unsigned)(((long)NTOK * (HP / 4) + 255) / 256), 256>>>(
        gu, hbuf, (long)NTOK * (HP / 4));
    k_hgemm<false, false><<<dim3(DIMC / 128, NTOK / 128, 1), 256, DYN_BYTES>>>(
        hbuf, w2t, out, HP, HP, HP, DIMC, 0L);

    // ---- routed experts ----
    k_hgemm<true, true><<<dim3(HP2 / 128, MAXROWS / 128, NEXP), 256, DYN_BYTES>>>(
        xh, e13, gu, DIMC, DIMC, DIMC, HP2, (long)HP2 * DIMC);
    k_silumul<<<(unsigned)(((long)MAXROWS * (HP / 4) + 255) / 256), 256>>>(
        gu, hbuf, (long)MAXROWS * (HP / 4));
    k_hgemm<false, true><<<dim3(DIMC / 128, MAXROWS / 128, NEXP), 256, DYN_BYTES>>>(
        hbuf, e2t, yb, HP, HP, HP, DIMC, (long)DIMC * HP);

    k_combine<<<(NTOK * (DIMC / 4) + 255) / 256, 256>>>(out);
}

// round 7
// speedup vs baseline: 1.5056x; 1.1354x over previous
#include <cuda_runtime.h>
#include <cuda_fp16.h>
#include <cstdint>
#include <cstddef>

#define DIMC 2048
#define HIDC 2730
#define HP   2816           // HID padded to multiple of 128 (N-tile) and 32 (K-chunk)
#define HP2  (2 * HP)       // gate+up concatenated
#define NEXP 8
#define NTOK 8192
#define MAXROWS 17408       // 2*NTOK + NEXP*127, rounded up to 128

// ---------------- scratch (static __device__, no allocs) ----------------
__device__ __half g_xh[(size_t)NTOK * DIMC];
__device__ __half g_w13T[(size_t)HP2 * DIMC];            // [N=2HP, K=DIMC]
__device__ __half g_w2T[(size_t)DIMC * HP];              // [N=DIMC, K=HP]
__device__ __half g_e13T[(size_t)NEXP * HP2 * DIMC];
__device__ __half g_e2T[(size_t)NEXP * DIMC * HP];
__device__ float  g_gu[(size_t)MAXROWS * HP2];           // gate|up GEMM output
__device__ __half g_h[(size_t)MAXROWS * HP];             // silu(gate)*up
__device__ float  g_y[(size_t)MAXROWS * DIMC];
__device__ int    g_counts[NEXP];
__device__ int    g_off[NEXP + 1];
__device__ int    g_cursor[NEXP];
__device__ int    g_rows[MAXROWS];
__device__ int    g_te[NTOK * 2];
__device__ int    g_slots[NTOK * 2];
__device__ float  g_wts[NTOK * 2];

// ---------------- helpers ----------------
__device__ __forceinline__ void cpasync16(uint32_t dst, const void* src) {
    asm volatile("cp.async.cg.shared.global [%0], [%1], 16;\n" :: "r"(dst), "l"(src));
}

__device__ __forceinline__ void ldsm4(uint32_t& r0, uint32_t& r1, uint32_t& r2, uint32_t& r3,
                                      uint32_t addr) {
    asm volatile("ldmatrix.sync.aligned.m8n8.x4.shared.b16 {%0,%1,%2,%3}, [%4];"
        : "=r"(r0), "=r"(r1), "=r"(r2), "=r"(r3) : "r"(addr));
}

// smem: rows of 32 halves (64B), 16B chunks XOR-swizzled by row bits 1-2
__device__ __forceinline__ uint32_t swdst(int row, int c) {
    return (uint32_t)(row * 64 + ((c ^ ((row >> 1) & 3)) << 4));
}

__device__ __forceinline__ void mma_f16(float c[4], const uint32_t a[4], const uint32_t b[2]) {
    asm volatile(
        "mma.sync.aligned.m16n8k16.row.col.f32.f16.f16.f32 "
        "{%0,%1,%2,%3}, {%4,%5,%6,%7}, {%8,%9}, {%0,%1,%2,%3};\n"
        : "+f"(c[0]), "+f"(c[1]), "+f"(c[2]), "+f"(c[3])
        : "r"(a[0]), "r"(a[1]), "r"(a[2]), "r"(a[3]), "r"(b[0]), "r"(b[1]));
}

// ---------------- small kernels ----------------
__global__ void k_tohalf(const float* __restrict__ in, __half* __restrict__ out, long n4) {
    long i = (long)blockIdx.x * blockDim.x + threadIdx.x;
    if (i >= n4) return;
    float4 v = reinterpret_cast<const float4*>(in)[i];
    __half2 h0 = __floats2half2_rn(v.x, v.y);
    __half2 h1 = __floats2half2_rn(v.z, v.w);
    uint2 u;
    u.x = *reinterpret_cast<uint32_t*>(&h0);
    u.y = *reinterpret_cast<uint32_t*>(&h1);
    reinterpret_cast<uint2*>(out)[i] = u;
}

__global__ void k_trans(const float* __restrict__ in, __half* __restrict__ out,
                        int R, int C, int CP, int RP, long inStride, long outStride) {
    __shared__ float t[32][33];
    const float* ip = in + (size_t)blockIdx.z * inStride;
    __half* op = out + (size_t)blockIdx.z * outStride;
    int c0 = blockIdx.x * 32, r0 = blockIdx.y * 32;
    int tx = threadIdx.x, ty = threadIdx.y;   // 32 x 8
    #pragma unroll
    for (int i = 0; i < 32; i += 8) {
        int r = r0 + ty + i, c = c0 + tx;
        t[ty + i][tx] = (r < R && c < C) ? ip[(size_t)r * C + c] : 0.f;
    }
    __syncthreads();
    #pragma unroll
    for (int i = 0; i < 32; i += 8) {
        int oc = c0 + ty + i, orr = r0 + tx;
        if (oc < CP && orr < RP)
            op[(size_t)oc * RP + orr] = __float2half_rn(t[tx][ty + i]);
    }
}

__global__ void k_init() {
    int i = blockIdx.x * blockDim.x + threadIdx.x;
    if (i < NEXP) g_counts[i] = 0;
    if (i < MAXROWS) g_rows[i] = 0;
}

__global__ void k_router(const float* __restrict__ x, const float* __restrict__ rw) {
    int gt = blockIdx.x * blockDim.x + threadIdx.x;
    int warp = gt >> 5;
    int lane = gt & 31;
    if (warp >= NTOK) return;
    const float* xr = x + (size_t)warp * DIMC;
    float acc[8] = {0.f,0.f,0.f,0.f,0.f,0.f,0.f,0.f};
    for (int i = 0; i < DIMC / 32; i++) {
        int d = i * 32 + lane;
        float xv = xr[d];
        const float4* p = reinterpret_cast<const float4*>(rw + (size_t)d * NEXP);
        float4 r0 = p[0], r1 = p[1];
        acc[0] += xv * r0.x; acc[1] += xv * r0.y; acc[2] += xv * r0.z; acc[3] += xv * r0.w;
        acc[4] += xv * r1.x; acc[5] += xv * r1.y; acc[6] += xv * r1.z; acc[7] += xv * r1.w;
    }
    #pragma unroll
    for (int e = 0; e < 8; e++) {
        #pragma unroll
        for (int o = 16; o > 0; o >>= 1) acc[e] += __shfl_xor_sync(0xffffffffu, acc[e], o);
    }
    if (lane == 0) {
        int e0 = 0; float l0 = acc[0];
        #pragma unroll
        for (int e = 1; e < 8; e++) if (acc[e] > l0) { l0 = acc[e]; e0 = e; }
        int e1 = 0; float l1 = -3.4e38f;
        #pragma unroll
        for (int e = 0; e < 8; e++) if (e != e0 && acc[e] > l1) { l1 = acc[e]; e1 = e; }
        float w0 = 1.f / (1.f + __expf(l1 - l0));
        g_te[2 * warp] = e0; g_te[2 * warp + 1] = e1;
        g_wts[2 * warp] = w0; g_wts[2 * warp + 1] = 1.f - w0;
        atomicAdd(&g_counts[e0], 1);
        atomicAdd(&g_counts[e1], 1);
    }
}

__global__ void k_scan() {
    if (threadIdx.x == 0 && blockIdx.x == 0) {
        int o = 0;
        for (int e = 0; e < NEXP; e++) {
            g_off[e] = o;
            g_cursor[e] = o;
            o += (g_counts[e] + 127) & ~127;
        }
        g_off[NEXP] = o;
    }
}

__global__ void k_assign() {
    int t = blockIdx.x * blockDim.x + threadIdx.x;
    if (t >= NTOK) return;
    #pragma unroll
    for (int k = 0; k < 2; k++) {
        int e = g_te[2 * t + k];
        int p = atomicAdd(&g_cursor[e], 1);
        g_rows[p] = t;
        g_slots[2 * t + k] = p;
    }
}

__global__ void k_silumul(const float* __restrict__ gu, __half* __restrict__ h, long n4) {
    long i = (long)blockIdx.x * blockDim.x + threadIdx.x;
    if (i >= n4) return;
    long row = i / (HP / 4);
    int c4 = (int)(i % (HP / 4)) * 4;
    const float4 gv = *reinterpret_cast<const float4*>(gu + row * HP2 + c4);
    const float4 uv = *reinterpret_cast<const float4*>(gu + row * HP2 + HP + c4);
    float ox = gv.x / (1.f + __expf(-gv.x)) * uv.x;
    float oy = gv.y / (1.f + __expf(-gv.y)) * uv.y;
    float oz = gv.z / (1.f + __expf(-gv.z)) * uv.z;
    float ow = gv.w / (1.f + __expf(-gv.w)) * uv.w;
    __half2 h0 = __floats2half2_rn(ox, oy);
    __half2 h1 = __floats2half2_rn(oz, ow);
    uint2 u;
    u.x = *reinterpret_cast<uint32_t*>(&h0);
    u.y = *reinterpret_cast<uint32_t*>(&h1);
    *reinterpret_cast<uint2*>(h + row * HP + c4) = u;
}

__global__ void k_combine(float* __restrict__ out) {
    int i = blockIdx.x * blockDim.x + threadIdx.x;
    if (i >= NTOK * (DIMC / 4)) return;
    int t = i / (DIMC / 4);
    int c4 = i % (DIMC / 4);
    int s0 = g_slots[2 * t], s1 = g_slots[2 * t + 1];
    float w0 = g_wts[2 * t], w1 = g_wts[2 * t + 1];
    float4 y0 = reinterpret_cast<const float4*>(g_y + (size_t)s0 * DIMC)[c4];
    float4 y1 = reinterpret_cast<const float4*>(g_y + (size_t)s1 * DIMC)[c4];
    float4 o = reinterpret_cast<float4*>(out)[i];
    o.x += w0 * y0.x + w1 * y1.x;
    o.y += w0 * y0.y + w1 * y1.y;
    o.z += w0 * y0.z + w1 * y1.z;
    o.w += w0 * y0.w + w1 * y1.w;
    reinterpret_cast<float4*>(out)[i] = o;
}

// ---------------- FP16 GEMM: C = A @ B^T, 128x128x32 tiles, 4-stage, ldmatrix --
#define NSTG 4
#define TILE_BYTES 8192          // 128 rows * 64B
#define STG_BYTES  16384
#define DYN_BYTES  (NSTG * STG_BYTES)

template <bool GATHER, bool EXPERT>
__global__ void __launch_bounds__(256, 2)
k_hgemm(const __half* __restrict__ A, const __half* __restrict__ B,
        float* __restrict__ C, int K, int lda, int ldb, int ldc, long bStride) {
    extern __shared__ char smemRaw[];
    __shared__ int rIdx[128];

    int z = blockIdx.z;
    int off = 0;
    if (EXPERT) {
        off = g_off[z];
        int mcount = g_off[z + 1] - off;
        if ((int)blockIdx.y * 128 >= mcount) return;
    }
    int bm = blockIdx.y, bn = blockIdx.x;
    int tid = threadIdx.x;
    int lane = tid & 31, warp = tid >> 5;
    int g = lane >> 2, t4 = lane & 3;
    int wm = warp >> 1, wn = warp & 1;

    uint32_t base = (uint32_t)__cvta_generic_to_shared(smemRaw);

    if (tid < 128) {
        int r = off + bm * 128 + tid;
        rIdx[tid] = GATHER ? g_rows[r] : r;
    }
    __syncthreads();

    int lrow = tid & 127;
    int cpair = (tid >> 7) * 2;
    const __half* agp = A + (size_t)rIdx[lrow] * lda + cpair * 8;
    const __half* Bt = B + (size_t)z * bStride;
    const __half* bgp = Bt + (size_t)(bn * 128 + lrow) * ldb + cpair * 8;

    auto loadStage = [&](int kt, int s) {
        int k0 = kt * 32;
        uint32_t sa = base + s * STG_BYTES;
        uint32_t sb = sa + TILE_BYTES;
        cpasync16(sa + swdst(lrow, cpair),     agp + k0);
        cpasync16(sa + swdst(lrow, cpair + 1), agp + k0 + 8);
        cpasync16(sb + swdst(lrow, cpair),     bgp + k0);
        cpasync16(sb + swdst(lrow, cpair + 1), bgp + k0 + 8);
        asm volatile("cp.async.commit_group;\n");
    };

    // ldmatrix per-lane source rows/chunks (within the 128-row tile)
    // A (x4 per mt, 16 rows x 16 k): tiles {r0-7 klo, r8-15 klo, r0-7 khi, r8-15 khi}
    int arow[2], achunk0;
    #pragma unroll
    for (int mt = 0; mt < 2; mt++)
        arow[mt] = wm * 32 + mt * 16 + (lane & 7) + (lane & 8);
    achunk0 = lane >> 4;                     // 0: k0-7, 1: k8-15
    // B (x4 per nt-pair, tiles {nt0 klo, nt0 khi, nt1 klo, nt1 khi})
    int brow[4], bchunk0;
    #pragma unroll
    for (int p = 0; p < 4; p++)
        brow[p] = wn * 64 + p * 16 + (lane & 7) + ((lane >> 1) & 8);
    bchunk0 = (lane >> 3) & 1;

    float c[2][8][4] = {};

    int KT = K >> 5;
    loadStage(0, 0);
    loadStage(1, 1);
    loadStage(2, 2);
    for (int kt = 0; kt < KT; kt++) {
        asm volatile("cp.async.wait_group %0;\n" :: "n"(2));
        __syncthreads();
        if (kt + 3 < KT) loadStage(kt + 3, (kt + 3) & 3);
        else asm volatile("cp.async.commit_group;\n");
        int s = kt & 3;
        uint32_t sa = base + s * STG_BYTES;
        uint32_t sb = sa + TILE_BYTES;
        #pragma unroll
        for (int kk = 0; kk < 2; kk++) {
            uint32_t a[2][4];
            #pragma unroll
            for (int mt = 0; mt < 2; mt++)
                ldsm4(a[mt][0], a[mt][1], a[mt][2], a[mt][3],
                      sa + swdst(arow[mt], kk * 2 + achunk0));
            uint32_t bf[8][2];
            #pragma unroll
            for (int p = 0; p < 4; p++)
                ldsm4(bf[2 * p][0], bf[2 * p][1], bf[2 * p + 1][0], bf[2 * p + 1][1],
                      sb + swdst(brow[p], kk * 2 + bchunk0));
            #pragma unroll
            for (int mt = 0; mt < 2; mt++)
                #pragma unroll
                for (int nt = 0; nt < 8; nt++)
                    mma_f16(c[mt][nt], a[mt], bf[nt]);
        }
        __syncthreads();
    }

    #pragma unroll
    for (int mt = 0; mt < 2; mt++) {
        int rr = off + bm * 128 + wm * 32 + mt * 16 + g;
        #pragma unroll
        for (int nt = 0; nt < 8; nt++) {
            int cc = bn * 128 + wn * 64 + nt * 8 + 2 * t4;
            *reinterpret_cast<float2*>(C + (size_t)rr * ldc + cc) =
                make_float2(c[mt][nt][0], c[mt][nt][1]);
            *reinterpret_cast<float2*>(C + (size_t)(rr + 8) * ldc + cc) =
                make_float2(c[mt][nt][2], c[mt][nt][3]);
        }
    }
}

// ---------------- host ----------------
extern "C" void kernel_launch(void* const* d_in, const int* in_sizes, int n_in,
                              void* d_out, int out_size) {
    const float* x   = (const float*)d_in[0];
    const float* rw  = (const float*)d_in[1];
    const float* sw1 = (const float*)d_in[2];
    const float* sw2 = (const float*)d_in[3];
    const float* sw3 = (const float*)d_in[4];
    const float* ew1 = (const float*)d_in[5];
    const float* ew2 = (const float*)d_in[6];
    const float* ew3 = (const float*)d_in[7];
    float* out = (float*)d_out;

    __half *xh, *w13, *w2t, *e13, *e2t, *hbuf;
    float *gu, *yb;
    cudaGetSymbolAddress((void**)&xh,   g_xh);
    cudaGetSymbolAddress((void**)&w13,  g_w13T);
    cudaGetSymbolAddress((void**)&w2t,  g_w2T);
    cudaGetSymbolAddress((void**)&e13,  g_e13T);
    cudaGetSymbolAddress((void**)&e2t,  g_e2T);
    cudaGetSymbolAddress((void**)&hbuf, g_h);
    cudaGetSymbolAddress((void**)&gu,   g_gu);
    cudaGetSymbolAddress((void**)&yb,   g_y);

    cudaFuncSetAttribute(k_hgemm<false, false>, cudaFuncAttributeMaxDynamicSharedMemorySize, DYN_BYTES);
    cudaFuncSetAttribute(k_hgemm<true,  true >, cudaFuncAttributeMaxDynamicSharedMemorySize, DYN_BYTES);
    cudaFuncSetAttribute(k_hgemm<false, true >, cudaFuncAttributeMaxDynamicSharedMemorySize, DYN_BYTES);

    k_init<<<(MAXROWS + 255) / 256, 256>>>();
    k_tohalf<<<((NTOK * DIMC / 4) + 255) / 256, 256>>>(x, xh, (long)NTOK * DIMC / 4);

    dim3 tb(32, 8);
    k_trans<<<dim3(HP / 32, DIMC / 32, 1), tb>>>(sw1, w13,                     DIMC, HIDC, HP, DIMC, 0, 0);
    k_trans<<<dim3(HP / 32, DIMC / 32, 1), tb>>>(sw3, w13 + (size_t)HP * DIMC, DIMC, HIDC, HP, DIMC, 0, 0);
    k_trans<<<dim3(HP / 32, DIMC / 32, NEXP), tb>>>(ew1, e13, DIMC, HIDC, HP, DIMC,
                                                    (long)DIMC * HIDC, (long)HP2 * DIMC);
    k_trans<<<dim3(HP / 32, DIMC / 32, NEXP), tb>>>(ew3, e13 + (size_t)HP * DIMC, DIMC, HIDC, HP, DIMC,
                                                    (long)DIMC * HIDC, (long)HP2 * DIMC);
    k_trans<<<dim3(DIMC / 32, HP / 32, 1), tb>>>(sw2, w2t, HIDC, DIMC, DIMC, HP, 0, 0);
    k_trans<<<dim3(DIMC / 32, HP / 32, NEXP), tb>>>(ew2, e2t, HIDC, DIMC, DIMC, HP,
                                                    (long)HIDC * DIMC, (long)DIMC * HP);

    k_router<<<(NTOK * 32 + 255) / 256, 256>>>(x, rw);
    k_scan<<<1, 32>>>();
    k_assign<<<(NTOK + 255) / 256, 256>>>();

    // ---- shared expert ----
    k_hgemm<false, false><<<dim3(HP2 / 128, NTOK / 128, 1), 256, DYN_BYTES>>>(
        xh, w13, gu, DIMC, DIMC, DIMC, HP2, 0L);
    k_silumul<<<(unsigned)(((long)NTOK * (HP / 4) + 255) / 256), 256>>>(
        gu, hbuf, (long)NTOK * (HP / 4));
    k_hgemm<false, false><<<dim3(DIMC / 128, NTOK / 128, 1), 256, DYN_BYTES>>>(
        hbuf, w2t, out, HP, HP, HP, DIMC, 0L);

    // ---- routed experts ----
    k_hgemm<true, true><<<dim3(HP2 / 128, MAXROWS / 128, NEXP), 256, DYN_BYTES>>>(
        xh, e13, gu, DIMC, DIMC, DIMC, HP2, (long)HP2 * DIMC);
    k_silumul<<<(unsigned)(((long)MAXROWS * (HP / 4) + 255) / 256), 256>>>(
        gu, hbuf, (long)MAXROWS * (HP / 4));
    k_hgemm<false, true><<<dim3(DIMC / 128, MAXROWS / 128, NEXP), 256, DYN_BYTES>>>(
        hbuf, e2t, yb, HP, HP, HP, DIMC, (long)DIMC * HP);

    k_combine<<<(NTOK * (DIMC / 4) + 255) / 256, 256>>>(out);
}